// round 1
// baseline (speedup 1.0000x reference)
#include <cuda_runtime.h>
#include <cuda_bf16.h>

#define N_NODES 100000
#define N_EDGES 1000000
#define HID 64
#define NGRAPH 512
#define NCLS 2

// Scratch (device globals; no allocation allowed)
__device__ __align__(128) float g_deg[N_NODES];
__device__ __align__(128) float g_dinv[N_NODES];
__device__ __align__(128) float g_norm[N_EDGES];
__device__ __align__(128) float g_xw[N_NODES * HID];
__device__ __align__(128) float g_aggA[N_NODES * HID];
__device__ __align__(128) float g_aggB[N_NODES * HID];
__device__ __align__(128) float g_pooled[NGRAPH * HID];
__device__ __align__(128) float g_cnt[NGRAPH];

__device__ __forceinline__ void red_add_v4(float* addr, float a, float b, float c, float d) {
    asm volatile("red.global.add.v4.f32 [%0], {%1, %2, %3, %4};"
                 :: "l"(addr), "f"(a), "f"(b), "f"(c), "f"(d)
                 : "memory");
}

__global__ void zero_f(float* __restrict__ p, int n) {
    int i = blockIdx.x * blockDim.x + threadIdx.x;
    if (i < n) p[i] = 0.0f;
}

// deg[dst] += w[e]
__global__ void deg_scatter(const int* __restrict__ ei, const float* __restrict__ w) {
    int e = blockIdx.x * blockDim.x + threadIdx.x;
    if (e < N_EDGES) atomicAdd(&g_deg[ei[N_EDGES + e]], w[e]);
}

// dinv = rsqrt(deg + 2)  (deg+2 > 0 always, but keep guard to match reference)
__global__ void dinv_k() {
    int i = blockIdx.x * blockDim.x + threadIdx.x;
    if (i < N_NODES) {
        float d = g_deg[i] + 2.0f;
        g_dinv[i] = (d > 0.0f) ? rsqrtf(d) : 0.0f;
    }
}

// norm[e] = dinv[src] * w[e] * dinv[dst]
__global__ void norm_k(const int* __restrict__ ei, const float* __restrict__ w) {
    int e = blockIdx.x * blockDim.x + threadIdx.x;
    if (e < N_EDGES) {
        int s = ei[e];
        int d = ei[N_EDGES + e];
        g_norm[e] = g_dinv[s] * w[e] * g_dinv[d];
    }
}

// Y[N,64] = maybe_relu(X[N,64]) @ W[64,64].  16 rows per block, 256 threads.
// Each thread holds one W column in registers; X tile staged in shared.
__global__ __launch_bounds__(256) void gemm64(const float* __restrict__ X,
                                              const float* __restrict__ W,
                                              float* __restrict__ Y,
                                              int reluIn) {
    __shared__ float sX[16][64];
    int tid = threadIdx.x;
    int j = tid & 63;        // output column
    int q = tid >> 6;        // 0..3 (row group)

    float wreg[64];
#pragma unroll
    for (int k = 0; k < 64; k++) wreg[k] = W[k * 64 + j];

    int rowBase = blockIdx.x * 16;
    // stage 16x64 tile: each thread loads one float4
    int rr = tid >> 4;              // 0..15
    int cc = (tid & 15) << 2;       // 0,4,...,60
    int gr = rowBase + rr;
    float4 v = make_float4(0.f, 0.f, 0.f, 0.f);
    if (gr < N_NODES) v = *reinterpret_cast<const float4*>(X + gr * 64 + cc);
    if (reluIn) {
        v.x = fmaxf(v.x, 0.f); v.y = fmaxf(v.y, 0.f);
        v.z = fmaxf(v.z, 0.f); v.w = fmaxf(v.w, 0.f);
    }
    *reinterpret_cast<float4*>(&sX[rr][cc]) = v;
    __syncthreads();

#pragma unroll
    for (int m = 0; m < 4; m++) {
        int r = (q << 2) + m;
        float acc = 0.f;
#pragma unroll
        for (int k = 0; k < 64; k += 4) {
            float4 xv = *reinterpret_cast<const float4*>(&sX[r][k]);
            acc += xv.x * wreg[k] + xv.y * wreg[k + 1]
                 + xv.z * wreg[k + 2] + xv.w * wreg[k + 3];
        }
        int go = rowBase + r;
        if (go < N_NODES) Y[go * 64 + j] = acc;
    }
}

// agg[i] = b[c] + 2*dinv[node]^2 * xw[i]   (self-loop term + bias; also zeroes base)
__global__ void init_self(float* __restrict__ agg, const float* __restrict__ b) {
    int t = blockIdx.x * blockDim.x + threadIdx.x;
    if (t >= N_NODES * 16) return;
    int node = t >> 4;
    int c4 = (t & 15) << 2;
    float s = g_dinv[node];
    s = 2.0f * s * s;
    float4 xv = *reinterpret_cast<const float4*>(g_xw + node * 64 + c4);
    float4 bv = *reinterpret_cast<const float4*>(b + c4);
    float4 o = make_float4(bv.x + s * xv.x, bv.y + s * xv.y,
                           bv.z + s * xv.z, bv.w + s * xv.w);
    *reinterpret_cast<float4*>(agg + node * 64 + c4) = o;
}

// agg[dst] += norm[e] * xw[src]   — 16 threads per edge, v4 RED atomics
__global__ void edge_scatter(const int* __restrict__ ei, float* __restrict__ agg) {
    int t = blockIdx.x * blockDim.x + threadIdx.x;
    int e = t >> 4;
    if (e >= N_EDGES) return;
    int c4 = (t & 15) << 2;
    int src = ei[e];
    int dst = ei[N_EDGES + e];
    float nm = g_norm[e];
    float4 v = *reinterpret_cast<const float4*>(g_xw + src * 64 + c4);
    red_add_v4(agg + dst * 64 + c4, nm * v.x, nm * v.y, nm * v.z, nm * v.w);
}

// pooled[batch[node]] += h[node];  cnt[batch[node]] += 1
__global__ void pool_acc(const float* __restrict__ h, const int* __restrict__ batch) {
    int t = blockIdx.x * blockDim.x + threadIdx.x;
    if (t >= N_NODES * 16) return;
    int node = t >> 4;
    int c = t & 15;
    int g = batch[node];
    float4 v = *reinterpret_cast<const float4*>(h + node * 64 + (c << 2));
    red_add_v4(g_pooled + g * 64 + (c << 2), v.x, v.y, v.z, v.w);
    if (c == 0) atomicAdd(&g_cnt[g], 1.0f);
}

// out[g,c] = bl[c] + (pooled[g]/max(cnt,1)) . Wl[:,c]
__global__ void final_k(const float* __restrict__ Wl, const float* __restrict__ bl,
                        float* __restrict__ out) {
    int t = blockIdx.x * blockDim.x + threadIdx.x;
    if (t >= NGRAPH * NCLS) return;
    int g = t >> 1;
    int c = t & 1;
    float inv = 1.0f / fmaxf(g_cnt[g], 1.0f);
    float acc = 0.f;
#pragma unroll
    for (int k = 0; k < 64; k++) acc += g_pooled[g * 64 + k] * Wl[k * NCLS + c];
    out[t] = bl[c] + acc * inv;
}

extern "C" void kernel_launch(void* const* d_in, const int* in_sizes, int n_in,
                              void* d_out, int out_size) {
    const float* x     = (const float*)d_in[0];
    const int*   ei    = (const int*)  d_in[1];
    const float* w     = (const float*)d_in[2];
    const int*   batch = (const int*)  d_in[3];
    const float* W1    = (const float*)d_in[4];
    const float* b1    = (const float*)d_in[5];
    const float* W2    = (const float*)d_in[6];
    const float* b2    = (const float*)d_in[7];
    const float* W3    = (const float*)d_in[8];
    const float* b3    = (const float*)d_in[9];
    const float* Wl    = (const float*)d_in[10];
    const float* bl    = (const float*)d_in[11];
    float* out = (float*)d_out;

    float *p_deg, *p_xw, *p_aggA, *p_aggB, *p_pooled, *p_cnt;
    cudaGetSymbolAddress((void**)&p_deg,    g_deg);
    cudaGetSymbolAddress((void**)&p_xw,     g_xw);
    cudaGetSymbolAddress((void**)&p_aggA,   g_aggA);
    cudaGetSymbolAddress((void**)&p_aggB,   g_aggB);
    cudaGetSymbolAddress((void**)&p_pooled, g_pooled);
    cudaGetSymbolAddress((void**)&p_cnt,    g_cnt);

    const int T = 256;
    int gN   = (N_NODES + T - 1) / T;
    int gE   = (N_EDGES + T - 1) / T;
    int gNF  = (N_NODES * 16 + T - 1) / T;   // node*feat4
    int gEF  = (N_EDGES * 16 + T - 1) / T;   // edge*feat4
    int gRow = (N_NODES + 15) / 16;

    // --- normalization (computed once, reused by all 3 layers) ---
    zero_f<<<gN, T>>>(p_deg, N_NODES);
    deg_scatter<<<gE, T>>>(ei, w);
    dinv_k<<<gN, T>>>();
    norm_k<<<gE, T>>>(ei, w);

    // --- layer 1: x -> aggA (relu folded into next gemm) ---
    gemm64<<<gRow, T>>>(x, W1, p_xw, 0);
    init_self<<<gNF, T>>>(p_aggA, b1);
    edge_scatter<<<gEF, T>>>(ei, p_aggA);

    // --- layer 2: relu(aggA) -> aggB ---
    gemm64<<<gRow, T>>>(p_aggA, W2, p_xw, 1);
    init_self<<<gNF, T>>>(p_aggB, b2);
    edge_scatter<<<gEF, T>>>(ei, p_aggB);

    // --- layer 3: relu(aggB) -> aggA (no relu on output) ---
    gemm64<<<gRow, T>>>(p_aggB, W3, p_xw, 1);
    init_self<<<gNF, T>>>(p_aggA, b3);
    edge_scatter<<<gEF, T>>>(ei, p_aggA);

    // --- pooling + classifier head ---
    zero_f<<<(NGRAPH * HID + T - 1) / T, T>>>(p_pooled, NGRAPH * HID);
    zero_f<<<(NGRAPH + T - 1) / T, T>>>(p_cnt, NGRAPH);
    pool_acc<<<gNF, T>>>(p_aggA, batch);
    final_k<<<(NGRAPH * NCLS + T - 1) / T, T>>>(Wl, bl, out);
}

// round 2
// speedup vs baseline: 1.2915x; 1.2915x over previous
#include <cuda_runtime.h>
#include <cuda_bf16.h>

#define N_NODES 100000
#define N_EDGES 1000000
#define HID 64
#define NGRAPH 512
#define NCLS 2
#define NB1 ((N_NODES + 1023) / 1024)

// ---- scratch (device globals; allocation is forbidden) ----
__device__ __align__(128) float g_deg[N_NODES];
__device__ __align__(128) float g_dinv[N_NODES];
__device__ __align__(128) float g_xw[N_NODES * HID];
__device__ __align__(128) float g_aggA[N_NODES * HID];
__device__ __align__(128) float g_aggB[N_NODES * HID];
__device__ __align__(128) float g_pooled[NGRAPH * HID];
__device__ __align__(128) float g_gcnt[NGRAPH];
__device__ __align__(128) int   g_ecnt[N_NODES];     // in-degree counts
__device__ __align__(128) int   g_rowptr[N_NODES];   // exclusive prefix
__device__ __align__(128) int   g_cursor[N_NODES];   // fill cursors
__device__ __align__(128) int   g_bsums[1024];
__device__ __align__(128) int2  g_csr[N_EDGES];      // {src, norm-as-bits}

// ---------------- preprocessing ----------------

__global__ void zero_prep() {
    int i = blockIdx.x * blockDim.x + threadIdx.x;
    if (i < N_NODES) { g_deg[i] = 0.0f; g_ecnt[i] = 0; }
    if (i < NGRAPH * HID) g_pooled[i] = 0.0f;
    if (i < NGRAPH) g_gcnt[i] = 0.0f;
}

// deg[dst] += w[e]; ecnt[dst] += 1
__global__ void deg_count(const int* __restrict__ ei, const float* __restrict__ w) {
    int e = blockIdx.x * blockDim.x + threadIdx.x;
    if (e < N_EDGES) {
        int d = ei[N_EDGES + e];
        atomicAdd(&g_deg[d], w[e]);
        atomicAdd(&g_ecnt[d], 1);
    }
}

__global__ void dinv_k() {
    int i = blockIdx.x * blockDim.x + threadIdx.x;
    if (i < N_NODES) {
        float d = g_deg[i] + 2.0f;
        g_dinv[i] = (d > 0.0f) ? rsqrtf(d) : 0.0f;
    }
}

// block-local exclusive scan of ecnt -> rowptr (partial), block sums out
__global__ __launch_bounds__(1024) void scan1() {
    __shared__ int s[1024];
    int tid = threadIdx.x;
    int i = blockIdx.x * 1024 + tid;
    int v = (i < N_NODES) ? g_ecnt[i] : 0;
    s[tid] = v;
    __syncthreads();
#pragma unroll
    for (int off = 1; off < 1024; off <<= 1) {
        int t = (tid >= off) ? s[tid - off] : 0;
        __syncthreads();
        s[tid] += t;
        __syncthreads();
    }
    if (i < N_NODES) g_rowptr[i] = s[tid] - v;   // exclusive within block
    if (tid == 1023) g_bsums[blockIdx.x] = s[1023];
}

// scan the (<=1024) block sums, exclusive, in place
__global__ __launch_bounds__(1024) void scan2(int nb) {
    __shared__ int s[1024];
    int tid = threadIdx.x;
    int v = (tid < nb) ? g_bsums[tid] : 0;
    s[tid] = v;
    __syncthreads();
#pragma unroll
    for (int off = 1; off < 1024; off <<= 1) {
        int t = (tid >= off) ? s[tid - off] : 0;
        __syncthreads();
        s[tid] += t;
        __syncthreads();
    }
    if (tid < nb) g_bsums[tid] = s[tid] - v;
}

// add block offsets; produce rowptr and cursor copy
__global__ __launch_bounds__(1024) void scan3() {
    int i = blockIdx.x * 1024 + threadIdx.x;
    if (i < N_NODES) {
        int r = g_rowptr[i] + g_bsums[blockIdx.x];
        g_rowptr[i] = r;
        g_cursor[i] = r;
    }
}

// bucket-place edges; compute norm inline
__global__ void csr_fill(const int* __restrict__ ei, const float* __restrict__ w) {
    int e = blockIdx.x * blockDim.x + threadIdx.x;
    if (e >= N_EDGES) return;
    int s = ei[e];
    int d = ei[N_EDGES + e];
    float nm = g_dinv[s] * w[e] * g_dinv[d];
    int pos = atomicAdd(&g_cursor[d], 1);
    g_csr[pos] = make_int2(s, __float_as_int(nm));
}

// ---------------- dense compute ----------------

// Y[N,64] = maybe_relu(X[N,64]) @ W[64,64].  16 rows/block, 256 threads.
__global__ __launch_bounds__(256) void gemm64(const float* __restrict__ X,
                                              const float* __restrict__ W,
                                              float* __restrict__ Y,
                                              int reluIn) {
    __shared__ float sX[16][64];
    int tid = threadIdx.x;
    int j = tid & 63;
    int q = tid >> 6;

    float wreg[64];
#pragma unroll
    for (int k = 0; k < 64; k++) wreg[k] = W[k * 64 + j];

    int rowBase = blockIdx.x * 16;
    int rr = tid >> 4;
    int cc = (tid & 15) << 2;
    int gr = rowBase + rr;
    float4 v = make_float4(0.f, 0.f, 0.f, 0.f);
    if (gr < N_NODES) v = *reinterpret_cast<const float4*>(X + gr * 64 + cc);
    if (reluIn) {
        v.x = fmaxf(v.x, 0.f); v.y = fmaxf(v.y, 0.f);
        v.z = fmaxf(v.z, 0.f); v.w = fmaxf(v.w, 0.f);
    }
    *reinterpret_cast<float4*>(&sX[rr][cc]) = v;
    __syncthreads();

#pragma unroll
    for (int m = 0; m < 4; m++) {
        int r = (q << 2) + m;
        float acc = 0.f;
#pragma unroll
        for (int k = 0; k < 64; k += 4) {
            float4 xv = *reinterpret_cast<const float4*>(&sX[r][k]);
            acc += xv.x * wreg[k] + xv.y * wreg[k + 1]
                 + xv.z * wreg[k + 2] + xv.w * wreg[k + 3];
        }
        int go = rowBase + r;
        if (go < N_NODES) Y[go * 64 + j] = acc;
    }
}

// dst-centric SpMM: one warp per dst row. acc = b + 2*dinv^2*xw[dst] + sum(norm*xw[src]).
// POOL=1: instead of writing agg, RED-accumulate into pooled[batch[dst]] (+count).
template <int POOL>
__global__ __launch_bounds__(256) void spmm(const float* __restrict__ xw,
                                            const float* __restrict__ b,
                                            float* __restrict__ agg,
                                            const int* __restrict__ batch) {
    int warp = (blockIdx.x * 256 + threadIdx.x) >> 5;
    int lane = threadIdx.x & 31;
    if (warp >= N_NODES) return;
    int dst = warp;

    const float2* xw2 = reinterpret_cast<const float2*>(xw);
    float s = g_dinv[dst];
    s = 2.0f * s * s;
    float2 self = xw2[dst * 32 + lane];
    float2 bv = reinterpret_cast<const float2*>(b)[lane];
    float ax = bv.x + s * self.x;
    float ay = bv.y + s * self.y;

    int p = g_rowptr[dst];
    int end = p + g_ecnt[dst];

    for (; p + 4 <= end; p += 4) {
        int2 e0 = g_csr[p], e1 = g_csr[p + 1], e2 = g_csr[p + 2], e3 = g_csr[p + 3];
        float2 a0 = xw2[e0.x * 32 + lane];
        float2 a1 = xw2[e1.x * 32 + lane];
        float2 a2 = xw2[e2.x * 32 + lane];
        float2 a3 = xw2[e3.x * 32 + lane];
        float n0 = __int_as_float(e0.y), n1 = __int_as_float(e1.y);
        float n2 = __int_as_float(e2.y), n3 = __int_as_float(e3.y);
        ax += n0 * a0.x + n1 * a1.x + n2 * a2.x + n3 * a3.x;
        ay += n0 * a0.y + n1 * a1.y + n2 * a2.y + n3 * a3.y;
    }
    for (; p < end; p++) {
        int2 e0 = g_csr[p];
        float2 a0 = xw2[e0.x * 32 + lane];
        float n0 = __int_as_float(e0.y);
        ax += n0 * a0.x;
        ay += n0 * a0.y;
    }

    if (POOL) {
        int g = batch[dst];
        asm volatile("red.global.add.v2.f32 [%0], {%1, %2};"
                     :: "l"(g_pooled + g * 64 + lane * 2), "f"(ax), "f"(ay)
                     : "memory");
        if (lane == 0) atomicAdd(&g_gcnt[g], 1.0f);
    } else {
        reinterpret_cast<float2*>(agg)[dst * 32 + lane] = make_float2(ax, ay);
    }
}

// out[g,c] = bl[c] + (pooled[g]/max(cnt,1)) . Wl[:,c]
__global__ void final_k(const float* __restrict__ Wl, const float* __restrict__ bl,
                        float* __restrict__ out) {
    int t = blockIdx.x * blockDim.x + threadIdx.x;
    if (t >= NGRAPH * NCLS) return;
    int g = t >> 1;
    int c = t & 1;
    float inv = 1.0f / fmaxf(g_gcnt[g], 1.0f);
    float acc = 0.f;
#pragma unroll
    for (int k = 0; k < 64; k++) acc += g_pooled[g * 64 + k] * Wl[k * NCLS + c];
    out[t] = bl[c] + acc * inv;
}

extern "C" void kernel_launch(void* const* d_in, const int* in_sizes, int n_in,
                              void* d_out, int out_size) {
    const float* x     = (const float*)d_in[0];
    const int*   ei    = (const int*)  d_in[1];
    const float* w     = (const float*)d_in[2];
    const int*   batch = (const int*)  d_in[3];
    const float* W1    = (const float*)d_in[4];
    const float* b1    = (const float*)d_in[5];
    const float* W2    = (const float*)d_in[6];
    const float* b2    = (const float*)d_in[7];
    const float* W3    = (const float*)d_in[8];
    const float* b3    = (const float*)d_in[9];
    const float* Wl    = (const float*)d_in[10];
    const float* bl    = (const float*)d_in[11];
    float* out = (float*)d_out;

    float *p_xw, *p_aggA, *p_aggB;
    cudaGetSymbolAddress((void**)&p_xw,   g_xw);
    cudaGetSymbolAddress((void**)&p_aggA, g_aggA);
    cudaGetSymbolAddress((void**)&p_aggB, g_aggB);

    const int T = 256;
    int gN   = (N_NODES + T - 1) / T;
    int gE   = (N_EDGES + T - 1) / T;
    int gRow = (N_NODES + 15) / 16;
    int gWarp = (N_NODES * 32 + T - 1) / T;   // one warp per node

    // --- preprocessing: degrees, norm, CSR ---
    zero_prep<<<gN, T>>>();
    deg_count<<<gE, T>>>(ei, w);
    dinv_k<<<gN, T>>>();
    scan1<<<NB1, 1024>>>();
    scan2<<<1, 1024>>>(NB1);
    scan3<<<NB1, 1024>>>();
    csr_fill<<<gE, T>>>(ei, w);

    // --- layer 1 ---
    gemm64<<<gRow, T>>>(x, W1, p_xw, 0);
    spmm<0><<<gWarp, T>>>(p_xw, b1, p_aggA, batch);
    // --- layer 2 ---
    gemm64<<<gRow, T>>>(p_aggA, W2, p_xw, 1);
    spmm<0><<<gWarp, T>>>(p_xw, b2, p_aggB, batch);
    // --- layer 3 (pooling fused; agg never materialized) ---
    gemm64<<<gRow, T>>>(p_aggB, W3, p_xw, 1);
    spmm<1><<<gWarp, T>>>(p_xw, b3, nullptr, batch);

    // --- classifier head ---
    final_k<<<(NGRAPH * NCLS + T - 1) / T, T>>>(Wl, bl, out);
}